// round 11
// baseline (speedup 1.0000x reference)
#include <cuda_runtime.h>

#define NN 200000
#define NE 3200000
#define CAP 96
#define NEG_SLOPE 0.02f
#define XT 256                 // xgemm nodes per block
#define XS 132                 // xs row stride (floats); 132%4==0, bank stride 4

// ---- static device scratch (no allocation allowed) ----
__device__ __align__(16) float g_f0[NN * 16];
__device__ __align__(16) float g_f1[NN * 16];
__device__ float g_dinv[NN];
__device__ int   g_cursor[NN];              // after fill: degree (excl. self-loop)
__device__ __align__(16) int g_csr[(size_t)NN * CAP];

// ---------------- graph build: slot table ----------------

__global__ void k_zero(int n) {
    int i = blockIdx.x * blockDim.x + threadIdx.x;
    if (i < n) g_cursor[i] = 0;
}

__global__ void k_fill(const int* __restrict__ src, const int* __restrict__ dst, int E) {
    int e = blockIdx.x * blockDim.x + threadIdx.x;
    if (e < E) {
        int d = dst[e];
        int pos = atomicAdd(&g_cursor[d], 1);
        if (pos < CAP) g_csr[(size_t)d * CAP + pos] = src[e];
    }
}

__global__ void k_dinv(int n) {
    int i = blockIdx.x * blockDim.x + threadIdx.x;
    if (i < n) g_dinv[i] = rsqrtf((float)g_cursor[i] + 1.0f);
}

// -------- layer 1 GEMM: f0 = x @ W1 (raw) --------
// 256 nodes/block staged in smem (coalesced), 1 node/thread compute (FFMA-bound).

__global__ void __launch_bounds__(256) k_xgemm(const float* __restrict__ x,
                                               const float* __restrict__ W, int n) {
    extern __shared__ float sm[];
    float* xs = sm;                       // [XT][XS]
    float* Ws = sm + XT * XS;             // [128*16]
    int tid = threadIdx.x;

    for (int i = tid; i < 128 * 16; i += 256) Ws[i] = W[i];

    int base = blockIdx.x * XT;
    int nrows = n - base; if (nrows > XT) nrows = XT;
    const float4* xg = (const float4*)(x + (size_t)base * 128);
    for (int i = tid; i < nrows * 32; i += 256) {
        int r = i >> 5, c = i & 31;
        float4 v = xg[i];                 // flat coalesced stream
        *(float4*)&xs[r * XS + c * 4] = v;
    }
    __syncthreads();

    if (base + tid >= n) return;

    float acc[16];
#pragma unroll
    for (int j = 0; j < 16; j++) acc[j] = 0.0f;

    const float* xrow = &xs[tid * XS];
#pragma unroll 4
    for (int k4 = 0; k4 < 32; k4++) {
        float4 v = *(const float4*)&xrow[k4 * 4];
        const float4* wr = (const float4*)&Ws[k4 * 64];
#pragma unroll
        for (int r = 0; r < 4; r++) {
            float c = (r == 0) ? v.x : (r == 1) ? v.y : (r == 2) ? v.z : v.w;
#pragma unroll
            for (int q = 0; q < 4; q++) {
                float4 w = wr[r * 4 + q];
                acc[q * 4 + 0] += c * w.x;
                acc[q * 4 + 1] += c * w.y;
                acc[q * 4 + 2] += c * w.z;
                acc[q * 4 + 3] += c * w.w;
            }
        }
    }

    float4* A = (float4*)&g_f0[(size_t)(base + tid) * 16];
#pragma unroll
    for (int q = 0; q < 4; q++)
        A[q] = make_float4(acc[q * 4], acc[q * 4 + 1], acc[q * 4 + 2], acc[q * 4 + 3]);
}

// -------- establish invariant: f0 *= dinv (f-tilde) --------

__global__ void k_scale(int n) {
    int i = blockIdx.x * blockDim.x + threadIdx.x;   // one float4 per thread
    if (i < n * 4) {
        float d = g_dinv[i >> 2];
        float4 v = ((float4*)g_f0)[i];
        ((float4*)g_f0)[i] = make_float4(v.x * d, v.y * d, v.z * d, v.w * d);
    }
}

// -------- fused agg + bias + relu + GEMM + rescale --------
// 8 lanes per node; lane owns features {2j, 2j+1} (float2).
// Input holds f~ = dinv*f. raw = dd*(f~self + sum f~[s]).
// Output = dinv * (relu(raw+b) @ W). Index loads software-pipelined.

__global__ void __launch_bounds__(256) k_aggf(const float* __restrict__ b,
                                              const float* __restrict__ W,
                                              int n, int dir) {
    __shared__ float Ws[256];
    __shared__ float bs[16];
    Ws[threadIdx.x] = W[threadIdx.x];
    if (threadIdx.x < 16) bs[threadIdx.x] = b[threadIdx.x];
    __syncthreads();

    const float* fsrc = dir ? g_f1 : g_f0;
    float*       fdst = dir ? g_f0 : g_f1;

    int node = blockIdx.x * 32 + (threadIdx.x >> 3);
    int j2 = threadIdx.x & 7;
    unsigned mask = 0xFFu << (threadIdx.x & 24);
    if (node >= n) return;

    const float2* fs2 = (const float2*)fsrc;
    float2 sum = fs2[(size_t)node * 8 + j2];      // self (f~)
    int deg = g_cursor[node];
    if (deg > CAP) deg = CAP;
    const int4* rowv = (const int4*)&g_csr[(size_t)node * CAP];
    const int*  row  = (const int*)rowv;

    int nq = deg >> 2;                 // full quads
    if (nq > 0) {
        int4 s = rowv[0];
        for (int q = 1; q < nq; q++) {
            int4 sn = rowv[q];         // prefetch next quad
            float2 vA = fs2[(size_t)s.x * 8 + j2];
            float2 vB = fs2[(size_t)s.y * 8 + j2];
            float2 vC = fs2[(size_t)s.z * 8 + j2];
            float2 vD = fs2[(size_t)s.w * 8 + j2];
            sum.x += vA.x + vB.x + vC.x + vD.x;
            sum.y += vA.y + vB.y + vC.y + vD.y;
            s = sn;
        }
        float2 vA = fs2[(size_t)s.x * 8 + j2];
        float2 vB = fs2[(size_t)s.y * 8 + j2];
        float2 vC = fs2[(size_t)s.z * 8 + j2];
        float2 vD = fs2[(size_t)s.w * 8 + j2];
        sum.x += vA.x + vB.x + vC.x + vD.x;
        sum.y += vA.y + vB.y + vC.y + vD.y;
    }
    for (int k = nq << 2; k < deg; k++) {
        float2 v = fs2[(size_t)row[k] * 8 + j2];
        sum.x += v.x; sum.y += v.y;
    }

    float dd = g_dinv[node];
    int j0 = j2 * 2;
    float t0 = fmaxf(dd * sum.x + bs[j0], 0.0f);
    float t1 = fmaxf(dd * sum.y + bs[j0 + 1], 0.0f);

    float o0 = 0.0f, o1 = 0.0f;
#pragma unroll
    for (int kk = 0; kk < 8; kk++) {
        float ta = __shfl_sync(mask, t0, kk, 8);
        float tb = __shfl_sync(mask, t1, kk, 8);
        o0 += ta * Ws[(2 * kk) * 16 + j0]     + tb * Ws[(2 * kk + 1) * 16 + j0];
        o1 += ta * Ws[(2 * kk) * 16 + j0 + 1] + tb * Ws[(2 * kk + 1) * 16 + j0 + 1];
    }
    ((float2*)fdst)[(size_t)node * 8 + j2] = make_float2(dd * o0, dd * o1);
}

// -------- last aggregation: raw output (for MLP), input f~ --------

__global__ void __launch_bounds__(256) k_aggl(int n) {
    int node = blockIdx.x * 32 + (threadIdx.x >> 3);
    int j2 = threadIdx.x & 7;
    if (node >= n) return;

    const float2* fs2 = (const float2*)g_f0;
    float2 sum = fs2[(size_t)node * 8 + j2];
    int deg = g_cursor[node];
    if (deg > CAP) deg = CAP;
    const int4* rowv = (const int4*)&g_csr[(size_t)node * CAP];
    const int*  row  = (const int*)rowv;

    int nq = deg >> 2;
    if (nq > 0) {
        int4 s = rowv[0];
        for (int q = 1; q < nq; q++) {
            int4 sn = rowv[q];
            float2 vA = fs2[(size_t)s.x * 8 + j2];
            float2 vB = fs2[(size_t)s.y * 8 + j2];
            float2 vC = fs2[(size_t)s.z * 8 + j2];
            float2 vD = fs2[(size_t)s.w * 8 + j2];
            sum.x += vA.x + vB.x + vC.x + vD.x;
            sum.y += vA.y + vB.y + vC.y + vD.y;
            s = sn;
        }
        float2 vA = fs2[(size_t)s.x * 8 + j2];
        float2 vB = fs2[(size_t)s.y * 8 + j2];
        float2 vC = fs2[(size_t)s.z * 8 + j2];
        float2 vD = fs2[(size_t)s.w * 8 + j2];
        sum.x += vA.x + vB.x + vC.x + vD.x;
        sum.y += vA.y + vB.y + vC.y + vD.y;
    }
    for (int k = nq << 2; k < deg; k++) {
        float2 v = fs2[(size_t)row[k] * 8 + j2];
        sum.x += v.x; sum.y += v.y;
    }

    float dd = g_dinv[node];
    ((float2*)g_f1)[(size_t)node * 8 + j2] = make_float2(dd * sum.x, dd * sum.y);
}

// -------- final: h = f1 + b3 ; MLP ; log_softmax -> out --------

__global__ void k_final(const float* __restrict__ b3,
                        const float* __restrict__ M1, const float* __restrict__ mb1,
                        const float* __restrict__ M2, const float* __restrict__ mb2,
                        const float* __restrict__ M3, const float* __restrict__ mb3,
                        float* __restrict__ out, int n) {
    __shared__ float M1s[16 * 64];
    __shared__ float M2s[64 * 16];
    __shared__ float M3s[16 * 2];
    __shared__ float b3s[16], mb1s[64], mb2s[16], mb3s[2];
    for (int i = threadIdx.x; i < 1024; i += blockDim.x) { M1s[i] = M1[i]; M2s[i] = M2[i]; }
    if (threadIdx.x < 32) M3s[threadIdx.x] = M3[threadIdx.x];
    if (threadIdx.x < 16) { b3s[threadIdx.x] = b3[threadIdx.x]; mb2s[threadIdx.x] = mb2[threadIdx.x]; }
    if (threadIdx.x < 64) mb1s[threadIdx.x] = mb1[threadIdx.x];
    if (threadIdx.x < 2) mb3s[threadIdx.x] = mb3[threadIdx.x];
    __syncthreads();

    int node = blockIdx.x * blockDim.x + threadIdx.x;
    if (node >= n) return;

    float t[16];
    const float4* r = (const float4*)&g_f1[(size_t)node * 16];
#pragma unroll
    for (int q = 0; q < 4; q++) {
        float4 v = r[q];
        t[q * 4 + 0] = v.x + b3s[q * 4 + 0];
        t[q * 4 + 1] = v.y + b3s[q * 4 + 1];
        t[q * 4 + 2] = v.z + b3s[q * 4 + 2];
        t[q * 4 + 3] = v.w + b3s[q * 4 + 3];
    }

    float a1[64];
#pragma unroll
    for (int j = 0; j < 64; j++) a1[j] = mb1s[j];
#pragma unroll
    for (int k = 0; k < 16; k++) {
        float tv = t[k];
#pragma unroll
        for (int j = 0; j < 64; j++) a1[j] += tv * M1s[k * 64 + j];
    }
#pragma unroll
    for (int j = 0; j < 64; j++) a1[j] = (a1[j] >= 0.0f) ? a1[j] : a1[j] * NEG_SLOPE;

    float a2[16];
#pragma unroll
    for (int j = 0; j < 16; j++) a2[j] = mb2s[j];
#pragma unroll
    for (int k = 0; k < 64; k++) {
        float av = a1[k];
#pragma unroll
        for (int j = 0; j < 16; j++) a2[j] += av * M2s[k * 16 + j];
    }
#pragma unroll
    for (int j = 0; j < 16; j++) a2[j] = (a2[j] >= 0.0f) ? a2[j] : a2[j] * NEG_SLOPE;

    float l0 = mb3s[0], l1 = mb3s[1];
#pragma unroll
    for (int k = 0; k < 16; k++) {
        l0 += a2[k] * M3s[k * 2 + 0];
        l1 += a2[k] * M3s[k * 2 + 1];
    }
    float m = fmaxf(l0, l1);
    float lse = m + logf(expf(l0 - m) + expf(l1 - m));
    ((float2*)out)[node] = make_float2(l0 - lse, l1 - lse);
}

// ---------------- launch ----------------

extern "C" void kernel_launch(void* const* d_in, const int* in_sizes, int n_in,
                              void* d_out, int out_size) {
    const float* x   = (const float*)d_in[0];
    const int*   dat = (const int*)d_in[1];
    const float* W1  = (const float*)d_in[2];
    const float* b1  = (const float*)d_in[3];
    const float* W2  = (const float*)d_in[4];
    const float* b2  = (const float*)d_in[5];
    const float* W3  = (const float*)d_in[6];
    const float* b3  = (const float*)d_in[7];
    const float* M1  = (const float*)d_in[8];
    const float* mb1 = (const float*)d_in[9];
    const float* M2  = (const float*)d_in[10];
    const float* mb2 = (const float*)d_in[11];
    const float* M3  = (const float*)d_in[12];
    const float* mb3 = (const float*)d_in[13];
    float* out = (float*)d_out;

    int n = in_sizes[0] / 128;
    int E = in_sizes[1] / 2;
    const int* src = dat;
    const int* dst = dat + E;

    int nb = (n + 255) / 256;
    int eb = (E + 255) / 256;
    int xb = (n + XT - 1) / XT;
    int ab = (n + 31) / 32;
    int scb = (n * 4 + 255) / 256;
    int xsmem = (XT * XS + 128 * 16) * (int)sizeof(float);   // ~140 KB

    static cudaStream_t s_build = nullptr;
    static cudaEvent_t ev_start = nullptr, ev_build = nullptr;
    if (s_build == nullptr) {
        cudaStreamCreateWithFlags(&s_build, cudaStreamNonBlocking);
        cudaEventCreateWithFlags(&ev_start, cudaEventDisableTiming);
        cudaEventCreateWithFlags(&ev_build, cudaEventDisableTiming);
        cudaFuncSetAttribute(k_xgemm, cudaFuncAttributeMaxDynamicSharedMemorySize, xsmem);
    }

    // fork: graph build concurrent with xgemm
    cudaEventRecord(ev_start, 0);
    cudaStreamWaitEvent(s_build, ev_start, 0);
    k_zero<<<nb, 256, 0, s_build>>>(n);
    k_fill<<<eb, 256, 0, s_build>>>(src, dst, E);
    k_dinv<<<nb, 256, 0, s_build>>>(n);
    cudaEventRecord(ev_build, s_build);

    k_xgemm<<<xb, 256, xsmem>>>(x, W1, n);

    cudaStreamWaitEvent(0, ev_build, 0);

    k_scale<<<scb, 256>>>(n);            // f0 -> f~
    k_aggf<<<ab, 256>>>(b1, W2, n, 0);   // f0 -> f1 (f~)
    k_aggf<<<ab, 256>>>(b2, W3, n, 1);   // f1 -> f0 (f~)
    k_aggl<<<ab, 256>>>(n);              // f0 -> f1 (raw)
    k_final<<<nb, 256>>>(b3, M1, mb1, M2, mb2, M3, mb3, out, n);
}

// round 13
// speedup vs baseline: 1.1859x; 1.1859x over previous
#include <cuda_runtime.h>

#define NN 200000
#define NE 3200000
#define CAP 96
#define NEG_SLOPE 0.02f

// ---- static device scratch (no allocation allowed) ----
__device__ __align__(128) float g_f0[NN * 16];
__device__ __align__(128) float g_f1[NN * 16];
__device__ float g_dinv[NN];
__device__ int   g_cursor[NN];              // after fill: degree (excl. self-loop)
__device__ __align__(16) int g_csr[(size_t)NN * CAP];

// ---------------- graph build: slot table ----------------

__global__ void k_zero(int n) {
    int i = blockIdx.x * blockDim.x + threadIdx.x;
    if (i < n) g_cursor[i] = 0;
}

__global__ void k_fill(const int* __restrict__ src, const int* __restrict__ dst, int E) {
    int e = blockIdx.x * blockDim.x + threadIdx.x;
    if (e < E) {
        int d = dst[e];
        int pos = atomicAdd(&g_cursor[d], 1);
        if (pos < CAP) g_csr[(size_t)d * CAP + pos] = src[e];
    }
}

__global__ void k_dinv(int n) {
    int i = blockIdx.x * blockDim.x + threadIdx.x;
    if (i < n) g_dinv[i] = rsqrtf((float)g_cursor[i] + 1.0f);
}

// -------- layer 1 GEMM: f0 = x @ W1 (raw). 2 nodes/thread (proven 51.5us config) --------

__global__ void __launch_bounds__(256) k_xgemm(const float* __restrict__ x,
                                               const float* __restrict__ W,
                                               int n, int half) {
    __shared__ float Ws[128 * 16];
    for (int i = threadIdx.x; i < 128 * 16; i += 256) Ws[i] = W[i];
    __syncthreads();
    int t = blockIdx.x * 256 + threadIdx.x;
    if (t >= half) return;
    int n0 = t;
    int n1 = t + half;
    bool has1 = (n1 < n);
    int n1c = has1 ? n1 : n0;

    float acc0[16], acc1[16];
#pragma unroll
    for (int j = 0; j < 16; j++) { acc0[j] = 0.0f; acc1[j] = 0.0f; }

    const float4* xr0 = (const float4*)(x + (size_t)n0 * 128);
    const float4* xr1 = (const float4*)(x + (size_t)n1c * 128);
#pragma unroll 8
    for (int k4 = 0; k4 < 32; k4++) {
        float4 a = xr0[k4];
        float4 b = xr1[k4];
        const float4* wr = (const float4*)&Ws[k4 * 64];
#pragma unroll
        for (int r = 0; r < 4; r++) {
            float ca = (r == 0) ? a.x : (r == 1) ? a.y : (r == 2) ? a.z : a.w;
            float cb = (r == 0) ? b.x : (r == 1) ? b.y : (r == 2) ? b.z : b.w;
#pragma unroll
            for (int q = 0; q < 4; q++) {
                float4 w = wr[r * 4 + q];
                acc0[q * 4 + 0] += ca * w.x; acc0[q * 4 + 1] += ca * w.y;
                acc0[q * 4 + 2] += ca * w.z; acc0[q * 4 + 3] += ca * w.w;
                acc1[q * 4 + 0] += cb * w.x; acc1[q * 4 + 1] += cb * w.y;
                acc1[q * 4 + 2] += cb * w.z; acc1[q * 4 + 3] += cb * w.w;
            }
        }
    }

    float4* A = (float4*)&g_f0[(size_t)n0 * 16];
#pragma unroll
    for (int q = 0; q < 4; q++)
        A[q] = make_float4(acc0[q * 4], acc0[q * 4 + 1], acc0[q * 4 + 2], acc0[q * 4 + 3]);
    if (has1) {
        float4* B = (float4*)&g_f0[(size_t)n1 * 16];
#pragma unroll
        for (int q = 0; q < 4; q++)
            B[q] = make_float4(acc1[q * 4], acc1[q * 4 + 1], acc1[q * 4 + 2], acc1[q * 4 + 3]);
    }
}

// -------- establish invariant: f0 *= dinv (f-tilde) --------

__global__ void k_scale(int n) {
    int i = blockIdx.x * blockDim.x + threadIdx.x;   // one float4 per thread
    if (i < n * 4) {
        float d = g_dinv[i >> 2];
        float4 v = ((float4*)g_f0)[i];
        ((float4*)g_f0)[i] = make_float4(v.x * d, v.y * d, v.z * d, v.w * d);
    }
}

// -------- fused agg + bias + relu + GEMM + rescale --------
// 4 lanes per node; lane q owns features {4q..4q+3} (float4). 64 nodes/block.
// Input holds f~ = dinv*f. raw = dd*(f~self + sum f~[s]). Output = dinv*(relu(raw+b)@W).

__global__ void __launch_bounds__(256) k_aggf(const float* __restrict__ b,
                                              const float* __restrict__ W,
                                              int n, int dir) {
    __shared__ float Ws[256];
    __shared__ float bs[16];
    Ws[threadIdx.x] = W[threadIdx.x];
    if (threadIdx.x < 16) bs[threadIdx.x] = b[threadIdx.x];
    __syncthreads();

    const float* fsrc = dir ? g_f1 : g_f0;
    float*       fdst = dir ? g_f0 : g_f1;

    int node = blockIdx.x * 64 + (threadIdx.x >> 2);
    int q = threadIdx.x & 3;                       // float4 slot
    unsigned mask = 0xFu << (threadIdx.x & 28);    // width-4 group mask
    if (node >= n) return;

    const float4* fs4 = (const float4*)fsrc;
    float4 sum = fs4[(size_t)node * 4 + q];        // self (f~)
    int deg = g_cursor[node];
    if (deg > CAP) deg = CAP;
    const int4* rowv = (const int4*)&g_csr[(size_t)node * CAP];
    const int*  row  = (const int*)rowv;

    int k = 0;
    for (; k + 4 <= deg; k += 4) {
        int4 s = rowv[k >> 2];
        float4 vA = fs4[(size_t)s.x * 4 + q];
        float4 vB = fs4[(size_t)s.y * 4 + q];
        float4 vC = fs4[(size_t)s.z * 4 + q];
        float4 vD = fs4[(size_t)s.w * 4 + q];
        sum.x += vA.x + vB.x + vC.x + vD.x;
        sum.y += vA.y + vB.y + vC.y + vD.y;
        sum.z += vA.z + vB.z + vC.z + vD.z;
        sum.w += vA.w + vB.w + vC.w + vD.w;
    }
    for (; k < deg; k++) {
        float4 v = fs4[(size_t)row[k] * 4 + q];
        sum.x += v.x; sum.y += v.y; sum.z += v.z; sum.w += v.w;
    }

    float dd = g_dinv[node];
    int j0 = q * 4;
    float4 t;
    t.x = fmaxf(dd * sum.x + bs[j0 + 0], 0.0f);
    t.y = fmaxf(dd * sum.y + bs[j0 + 1], 0.0f);
    t.z = fmaxf(dd * sum.z + bs[j0 + 2], 0.0f);
    t.w = fmaxf(dd * sum.w + bs[j0 + 3], 0.0f);

    // 16x16 GEMM across 4-lane group: o_j = sum_k t_k * W[k][j], j in [4q,4q+4)
    float4 o = make_float4(0.f, 0.f, 0.f, 0.f);
#pragma unroll
    for (int kk = 0; kk < 4; kk++) {               // source lane kk holds t[4kk..4kk+3]
        float ta = __shfl_sync(mask, t.x, kk, 4);
        float tb = __shfl_sync(mask, t.y, kk, 4);
        float tc = __shfl_sync(mask, t.z, kk, 4);
        float td = __shfl_sync(mask, t.w, kk, 4);
        const float4 w0 = *(const float4*)&Ws[(4 * kk + 0) * 16 + j0];
        const float4 w1 = *(const float4*)&Ws[(4 * kk + 1) * 16 + j0];
        const float4 w2 = *(const float4*)&Ws[(4 * kk + 2) * 16 + j0];
        const float4 w3 = *(const float4*)&Ws[(4 * kk + 3) * 16 + j0];
        o.x += ta * w0.x + tb * w1.x + tc * w2.x + td * w3.x;
        o.y += ta * w0.y + tb * w1.y + tc * w2.y + td * w3.y;
        o.z += ta * w0.z + tb * w1.z + tc * w2.z + td * w3.z;
        o.w += ta * w0.w + tb * w1.w + tc * w2.w + td * w3.w;
    }
    ((float4*)fdst)[(size_t)node * 4 + q] = make_float4(dd * o.x, dd * o.y, dd * o.z, dd * o.w);
}

// -------- last aggregation: raw output (for MLP), input f~ --------

__global__ void __launch_bounds__(256) k_aggl(int n) {
    int node = blockIdx.x * 64 + (threadIdx.x >> 2);
    int q = threadIdx.x & 3;
    if (node >= n) return;

    const float4* fs4 = (const float4*)g_f0;
    float4 sum = fs4[(size_t)node * 4 + q];
    int deg = g_cursor[node];
    if (deg > CAP) deg = CAP;
    const int4* rowv = (const int4*)&g_csr[(size_t)node * CAP];
    const int*  row  = (const int*)rowv;

    int k = 0;
    for (; k + 4 <= deg; k += 4) {
        int4 s = rowv[k >> 2];
        float4 vA = fs4[(size_t)s.x * 4 + q];
        float4 vB = fs4[(size_t)s.y * 4 + q];
        float4 vC = fs4[(size_t)s.z * 4 + q];
        float4 vD = fs4[(size_t)s.w * 4 + q];
        sum.x += vA.x + vB.x + vC.x + vD.x;
        sum.y += vA.y + vB.y + vC.y + vD.y;
        sum.z += vA.z + vB.z + vC.z + vD.z;
        sum.w += vA.w + vB.w + vC.w + vD.w;
    }
    for (; k < deg; k++) {
        float4 v = fs4[(size_t)row[k] * 4 + q];
        sum.x += v.x; sum.y += v.y; sum.z += v.z; sum.w += v.w;
    }

    float dd = g_dinv[node];
    ((float4*)g_f1)[(size_t)node * 4 + q] =
        make_float4(dd * sum.x, dd * sum.y, dd * sum.z, dd * sum.w);
}

// -------- final: h = f1 + b3 ; MLP ; log_softmax -> out --------

__global__ void k_final(const float* __restrict__ b3,
                        const float* __restrict__ M1, const float* __restrict__ mb1,
                        const float* __restrict__ M2, const float* __restrict__ mb2,
                        const float* __restrict__ M3, const float* __restrict__ mb3,
                        float* __restrict__ out, int n) {
    __shared__ float M1s[16 * 64];
    __shared__ float M2s[64 * 16];
    __shared__ float M3s[16 * 2];
    __shared__ float b3s[16], mb1s[64], mb2s[16], mb3s[2];
    for (int i = threadIdx.x; i < 1024; i += blockDim.x) { M1s[i] = M1[i]; M2s[i] = M2[i]; }
    if (threadIdx.x < 32) M3s[threadIdx.x] = M3[threadIdx.x];
    if (threadIdx.x < 16) { b3s[threadIdx.x] = b3[threadIdx.x]; mb2s[threadIdx.x] = mb2[threadIdx.x]; }
    if (threadIdx.x < 64) mb1s[threadIdx.x] = mb1[threadIdx.x];
    if (threadIdx.x < 2) mb3s[threadIdx.x] = mb3[threadIdx.x];
    __syncthreads();

    int node = blockIdx.x * blockDim.x + threadIdx.x;
    if (node >= n) return;

    float t[16];
    const float4* r = (const float4*)&g_f1[(size_t)node * 16];
#pragma unroll
    for (int q = 0; q < 4; q++) {
        float4 v = r[q];
        t[q * 4 + 0] = v.x + b3s[q * 4 + 0];
        t[q * 4 + 1] = v.y + b3s[q * 4 + 1];
        t[q * 4 + 2] = v.z + b3s[q * 4 + 2];
        t[q * 4 + 3] = v.w + b3s[q * 4 + 3];
    }

    float a1[64];
#pragma unroll
    for (int j = 0; j < 64; j++) a1[j] = mb1s[j];
#pragma unroll
    for (int k = 0; k < 16; k++) {
        float tv = t[k];
#pragma unroll
        for (int j = 0; j < 64; j++) a1[j] += tv * M1s[k * 64 + j];
    }
#pragma unroll
    for (int j = 0; j < 64; j++) a1[j] = (a1[j] >= 0.0f) ? a1[j] : a1[j] * NEG_SLOPE;

    float a2[16];
#pragma unroll
    for (int j = 0; j < 16; j++) a2[j] = mb2s[j];
#pragma unroll
    for (int k = 0; k < 64; k++) {
        float av = a1[k];
#pragma unroll
        for (int j = 0; j < 16; j++) a2[j] += av * M2s[k * 16 + j];
    }
#pragma unroll
    for (int j = 0; j < 16; j++) a2[j] = (a2[j] >= 0.0f) ? a2[j] : a2[j] * NEG_SLOPE;

    float l0 = mb3s[0], l1 = mb3s[1];
#pragma unroll
    for (int k = 0; k < 16; k++) {
        l0 += a2[k] * M3s[k * 2 + 0];
        l1 += a2[k] * M3s[k * 2 + 1];
    }
    float m = fmaxf(l0, l1);
    float lse = m + logf(expf(l0 - m) + expf(l1 - m));
    ((float2*)out)[node] = make_float2(l0 - lse, l1 - lse);
}

// ---------------- launch ----------------

extern "C" void kernel_launch(void* const* d_in, const int* in_sizes, int n_in,
                              void* d_out, int out_size) {
    const float* x   = (const float*)d_in[0];
    const int*   dat = (const int*)d_in[1];
    const float* W1  = (const float*)d_in[2];
    const float* b1  = (const float*)d_in[3];
    const float* W2  = (const float*)d_in[4];
    const float* b2  = (const float*)d_in[5];
    const float* W3  = (const float*)d_in[6];
    const float* b3  = (const float*)d_in[7];
    const float* M1  = (const float*)d_in[8];
    const float* mb1 = (const float*)d_in[9];
    const float* M2  = (const float*)d_in[10];
    const float* mb2 = (const float*)d_in[11];
    const float* M3  = (const float*)d_in[12];
    const float* mb3 = (const float*)d_in[13];
    float* out = (float*)d_out;

    int n = in_sizes[0] / 128;
    int E = in_sizes[1] / 2;
    const int* src = dat;
    const int* dst = dat + E;

    int nb = (n + 255) / 256;
    int eb = (E + 255) / 256;
    int half = (n + 1) / 2;
    int xb = (half + 255) / 256;
    int ab = (n + 63) / 64;
    int scb = (n * 4 + 255) / 256;

    static cudaStream_t s_build = nullptr;
    static cudaEvent_t ev_start = nullptr, ev_build = nullptr;
    if (s_build == nullptr) {
        cudaStreamCreateWithFlags(&s_build, cudaStreamNonBlocking);
        cudaEventCreateWithFlags(&ev_start, cudaEventDisableTiming);
        cudaEventCreateWithFlags(&ev_build, cudaEventDisableTiming);
    }

    // fork: graph build concurrent with xgemm
    cudaEventRecord(ev_start, 0);
    cudaStreamWaitEvent(s_build, ev_start, 0);
    k_zero<<<nb, 256, 0, s_build>>>(n);
    k_fill<<<eb, 256, 0, s_build>>>(src, dst, E);
    k_dinv<<<nb, 256, 0, s_build>>>(n);
    cudaEventRecord(ev_build, s_build);

    k_xgemm<<<xb, 256>>>(x, W1, n, half);

    cudaStreamWaitEvent(0, ev_build, 0);

    k_scale<<<scb, 256>>>(n);            // f0 -> f~
    k_aggf<<<ab, 256>>>(b1, W2, n, 0);   // f0 -> f1 (f~)
    k_aggf<<<ab, 256>>>(b2, W3, n, 1);   // f1 -> f0 (f~)
    k_aggl<<<ab, 256>>>(n);              // f0 -> f1 (raw)
    k_final<<<nb, 256>>>(b3, M1, mb1, M2, mb2, M3, mb3, out, n);
}